// round 6
// baseline (speedup 1.0000x reference)
#include <cuda_runtime.h>

// ---------------------------------------------------------------------------
// DeformAttnwMotion fused kernel, round 5
//   R4 -> R5 changes:
//   1. Weight smem loads via LDS.128 (ulonglong2) -> smem crossbar no longer
//      the binding pipe (48 vs 64 fma cycles per c per SM).
//   2. grid = 128 persistent-ish blocks x 2 tile-units -> exactly 1 wave,
//      no 256/148 quantization penalty; Wk staged once per block.
//
// b=4, c=128, d=4096 (64x64), S=18 samples, OUT_C=128, 8 heads x 16 ch.
// Output layout in d_out (float32):
//   [0 , 2097152)            out      : (4,128,64,64)
//   [2097152 , 3276800)      kv0_attn : (32, 9, 4096)
//   [3276800 , 4456448)      kv1_attn : (32, 9, 4096)
// ---------------------------------------------------------------------------

typedef unsigned long long ull;

#define BB   4
#define CC   128
#define DD   4096
#define SS   18
#define OCH  128
#define NHD  8
#define HCH  16
#define FT   64            // pixels per tile-unit
#define UNITS_PER_BLOCK 2
#define GRID_X 128         // 256 units / 2
#define SCALE_F 0.25f

// Transposed weights scratch: [m][c][oc], m = 0:Wq 1:Wk 2:Wv
__device__ float g_WT[3 * CC * OCH];

__global__ void transpose_w_kernel(const float* __restrict__ Wq,
                                   const float* __restrict__ Wk,
                                   const float* __restrict__ Wv) {
    int idx = blockIdx.x * blockDim.x + threadIdx.x;       // 0 .. 49151
    if (idx >= 3 * CC * OCH) return;
    int m   = idx >> 14;
    int rem = idx & 16383;
    int r   = rem >> 7;     // oc
    int c   = rem & 127;    // c
    const float* W = (m == 0) ? Wq : (m == 1) ? Wk : Wv;
    g_WT[m * 16384 + c * OCH + r] = W[r * CC + c];
}

// ---------------- packed f32x2 helpers ----------------
__device__ __forceinline__ ull pack2(float lo, float hi) {
    ull r;
    asm("mov.b64 %0, {%1, %2};" : "=l"(r) : "f"(lo), "f"(hi));
    return r;
}
__device__ __forceinline__ float2 unpack2(ull v) {
    float2 r;
    asm("mov.b64 {%0, %1}, %2;" : "=f"(r.x), "=f"(r.y) : "l"(v));
    return r;
}
__device__ __forceinline__ ull fma2(ull a, ull b, ull c) {
    ull d;
    asm("fma.rn.f32x2 %0, %1, %2, %3;" : "=l"(d) : "l"(a), "l"(b), "l"(c));
    return d;
}
__device__ __forceinline__ ull mul2(ull a, ull b) {
    ull d;
    asm("mul.rn.f32x2 %0, %1, %2;" : "=l"(d) : "l"(a), "l"(b));
    return d;
}
__device__ __forceinline__ void cp16(float* dst, const float* src) {
    unsigned sa = (unsigned)__cvta_generic_to_shared(dst);
    asm volatile("cp.async.cg.shared.global [%0], [%1], 16;" :: "r"(sa), "l"(src));
}

// GEMM micro-pass: ra/rb[p] += W^T[c][oc0+2p..2p+1] * X[c][fi | fi+32]
// Weights read as LDS.128 (2 packed f32x2 per load). 16 FMA2 / c / thread.
__device__ __forceinline__ void proj_pass(const float* __restrict__ Wt,
                                          const float* __restrict__ X,
                                          int fi, int oc0,
                                          ull ra[8], ull rb[8]) {
#pragma unroll 8
    for (int c = 0; c < CC; ++c) {
        float xa = X[c * FT + fi];
        float xb = X[c * FT + fi + 32];
        ull xa2 = pack2(xa, xa);
        ull xb2 = pack2(xb, xb);
        const ulonglong2* wr =
            reinterpret_cast<const ulonglong2*>(Wt + c * OCH + oc0);
#pragma unroll
        for (int p = 0; p < 4; ++p) {
            ulonglong2 w = wr[p];               // LDS.128: 4 weight floats
            ra[2 * p]     = fma2(w.x, xa2, ra[2 * p]);
            rb[2 * p]     = fma2(w.x, xb2, rb[2 * p]);
            ra[2 * p + 1] = fma2(w.y, xa2, ra[2 * p + 1]);
            rb[2 * p + 1] = fma2(w.y, xb2, rb[2 * p + 1]);
        }
    }
}

__global__ void __launch_bounds__(256, 1)
deform_attn_kernel(const float* __restrict__ q,
                   const float* __restrict__ kv,
                   const float* __restrict__ bq,
                   const float* __restrict__ bk,
                   const float* __restrict__ bv,
                   float* __restrict__ out) {
    extern __shared__ float smem[];
    float* sWk = smem;               // 16384 floats : Wk^T [c][oc], whole block life
    float* sWv = smem + 16384;       // 16384 floats : Wq^T then Wv^T (per tile)
    float* sX0 = smem + 32768;       // 8192 : q tile, then kv ping buffer
    float* sX1 = smem + 40960;       // 8192 : kv pong buffer
    float* sB  = smem + 49152;       // 384  : bq | bk | bv

    const int t   = threadIdx.x;     // 256 threads
    const int fi  = t & 31;          // pixel lane; thread owns fi and fi+32
    const int g   = t >> 5;          // head 0..7
    const int oc0 = g * HCH;

    float* attn0 = out + (size_t)BB * OCH * DD;             // 2097152
    float* attn1 = attn0 + (size_t)BB * NHD * 9 * DD;       // +1179648

    // ------------- once per block: Wk^T + biases -----------------------------
    {
        const float4* gk = reinterpret_cast<const float4*>(g_WT + 16384); // WkT
        float4* dk = reinterpret_cast<float4*>(sWk);
#pragma unroll
        for (int i = 0; i < 16; ++i) {
            int idx = t + i * 256;
            dk[idx] = gk[idx];
        }
        if (t < 128) {
            sB[t]       = bq[t];
            sB[128 + t] = bk[t];
            sB[256 + t] = bv[t];
        }
    }

    // ------------- tile-unit loop (2 units, one wave, perfectly balanced) ----
    for (int it = 0; it < UNITS_PER_BLOCK; ++it) {
        const int unit = blockIdx.x + it * GRID_X;   // 0..255
        const int b    = unit >> 6;                  // batch
        const int f0   = (unit & 63) * FT;           // pixel-tile origin

        // phase 0: Wq^T -> sWv, q tile -> sX0, kv(s=0) -> sX1 (async)
        {
            const float4* gq = reinterpret_cast<const float4*>(g_WT);   // WqT
            float4* dq = reinterpret_cast<float4*>(sWv);
#pragma unroll
            for (int i = 0; i < 16; ++i) {
                int idx = t + i * 256;
                dq[idx] = gq[idx];
            }
#pragma unroll
            for (int i = 0; i < 8; ++i) {
                int idx = t + i * 256;
                int c = idx >> 4, f4 = idx & 15;
                reinterpret_cast<float4*>(sX0 + c * FT)[f4] =
                    reinterpret_cast<const float4*>(
                        q + ((size_t)(b * CC + c)) * DD + f0)[f4];
            }
#pragma unroll
            for (int i = 0; i < 8; ++i) {
                int idx = t + i * 256;
                int c = idx >> 4, f4 = idx & 15;
                cp16(sX1 + c * FT + f4 * 4,
                     kv + (((size_t)(b * CC + c)) * SS + 0) * DD + f0 + f4 * 4);
            }
            asm volatile("cp.async.commit_group;" ::: "memory");
        }
        __syncthreads();

        // q projection (sWv holds Wq^T)
        ull qpa[8], qpb[8];
#pragma unroll
        for (int p = 0; p < 8; ++p) {
            ull bb = pack2(sB[oc0 + 2 * p], sB[oc0 + 2 * p + 1]);
            qpa[p] = bb; qpb[p] = bb;
        }
        proj_pass(sWv, sX0, fi, oc0, qpa, qpb);
        __syncthreads();                 // done reading Wq^T and q tile

        {   // overwrite with Wv^T
            const float4* gv = reinterpret_cast<const float4*>(g_WT + 32768);
            float4* dv = reinterpret_cast<float4*>(sWv);
#pragma unroll
            for (int i = 0; i < 16; ++i) {
                int idx = t + i * 256;
                dv[idx] = gv[idx];
            }
        }
        __syncthreads();

        // online-softmax state
        const float NEG = -1e30f;
        float m_a = NEG, Z_a = 0.f, m_b = NEG, Z_b = 0.f;   // full softmax
        float m0a = NEG, Z0a = 0.f, m1a = NEG, Z1a = 0.f;   // half trackers px a
        float m0b = NEG, Z0b = 0.f, m1b = NEG, Z1b = 0.f;   // half trackers px b
        ull acc_a[8], acc_b[8];
#pragma unroll
        for (int p = 0; p < 8; ++p) { acc_a[p] = 0ull; acc_b[p] = 0ull; }

        // main sample loop
        for (int s = 0; s < SS; ++s) {
            float* cur = (s & 1) ? sX0 : sX1;
            float* nxt = (s & 1) ? sX1 : sX0;
            if (s < SS - 1) {
#pragma unroll
                for (int i = 0; i < 8; ++i) {
                    int idx = t + i * 256;
                    int c = idx >> 4, f4 = idx & 15;
                    cp16(nxt + c * FT + f4 * 4,
                         kv + (((size_t)(b * CC + c)) * SS + (s + 1)) * DD
                            + f0 + f4 * 4);
                }
                asm volatile("cp.async.commit_group;" ::: "memory");
                asm volatile("cp.async.wait_group 1;" ::: "memory");
            } else {
                asm volatile("cp.async.wait_group 0;" ::: "memory");
            }
            __syncthreads();

            // ---- K projection ----
            ull ka[8], kb[8];
#pragma unroll
            for (int p = 0; p < 8; ++p) {
                ull bbk = pack2(sB[128 + oc0 + 2 * p], sB[128 + oc0 + 2 * p + 1]);
                ka[p] = bbk; kb[p] = bbk;
            }
            proj_pass(sWk, cur, fi, oc0, ka, kb);

            // ---- logits ----
            ull da = 0ull, db = 0ull;
#pragma unroll
            for (int p = 0; p < 8; ++p) {
                da = fma2(qpa[p], ka[p], da);
                db = fma2(qpb[p], kb[p], db);
            }
            float2 dau = unpack2(da), dbu = unpack2(db);
            float a_a = (dau.x + dau.y) * SCALE_F;
            float a_b = (dbu.x + dbu.y) * SCALE_F;

            // stage raw logits into the attn output region (same thread re-reads)
            {
                float* base = (s < 9) ? attn0 : attn1;
                int ss = (s < 9) ? s : s - 9;
                size_t off = ((size_t)(b * NHD + g) * 9 + ss) * DD + f0 + fi;
                base[off]      = a_a;
                base[off + 32] = a_b;
            }

            // ---- per-half online (m, Z) ----
            if (s < 9) {
                float nm = fmaxf(m0a, a_a);
                Z0a = Z0a * __expf(m0a - nm) + __expf(a_a - nm); m0a = nm;
                nm = fmaxf(m0b, a_b);
                Z0b = Z0b * __expf(m0b - nm) + __expf(a_b - nm); m0b = nm;
            } else {
                float nm = fmaxf(m1a, a_a);
                Z1a = Z1a * __expf(m1a - nm) + __expf(a_a - nm); m1a = nm;
                nm = fmaxf(m1b, a_b);
                Z1b = Z1b * __expf(m1b - nm) + __expf(a_b - nm); m1b = nm;
            }

            // ---- full online softmax rescale ----
            float nma = fmaxf(m_a, a_a);
            float caf = __expf(m_a - nma), paf = __expf(a_a - nma);
            Z_a = Z_a * caf + paf; m_a = nma;
            float nmb = fmaxf(m_b, a_b);
            float cbf = __expf(m_b - nmb), pbf = __expf(a_b - nmb);
            Z_b = Z_b * cbf + pbf; m_b = nmb;

            ull ca2 = pack2(caf, caf), pa2 = pack2(paf, paf);
            ull cb2 = pack2(cbf, cbf), pb2 = pack2(pbf, pbf);

            // ---- V projection (reuse ka/kb as vp) ----
#pragma unroll
            for (int p = 0; p < 8; ++p) {
                ull bbv = pack2(sB[256 + oc0 + 2 * p], sB[256 + oc0 + 2 * p + 1]);
                ka[p] = bbv; kb[p] = bbv;
            }
            proj_pass(sWv, cur, fi, oc0, ka, kb);

            // acc = acc*corr + vp*p
#pragma unroll
            for (int p = 0; p < 8; ++p) {
                acc_a[p] = fma2(acc_a[p], ca2, mul2(ka[p], pa2));
                acc_b[p] = fma2(acc_b[p], cb2, mul2(kb[p], pb2));
            }
            __syncthreads();    // all readers of 'cur' done before refill
        }

        // epilogue: out = acc / Z
        {
            float ia = 1.f / Z_a, ib = 1.f / Z_b;
#pragma unroll
            for (int p = 0; p < 8; ++p) {
                float2 oa = unpack2(acc_a[p]);
                float2 ob = unpack2(acc_b[p]);
                size_t r0 = ((size_t)(b * OCH + oc0 + 2 * p)) * DD + f0 + fi;
                size_t r1 = r0 + DD;
                out[r0]      = oa.x * ia;
                out[r1]      = oa.y * ia;
                out[r0 + 32] = ob.x * ib;
                out[r1 + 32] = ob.y * ib;
            }
        }

        // epilogue: half softmaxes over staged logits
        {
            float i0a = 1.f / Z0a, i1a = 1.f / Z1a;
            float i0b = 1.f / Z0b, i1b = 1.f / Z1b;
            size_t baseoff = ((size_t)(b * NHD + g) * 9) * DD + f0 + fi;
#pragma unroll
            for (int ss = 0; ss < 9; ++ss) {
                size_t off = baseoff + (size_t)ss * DD;
                float la  = attn0[off], lb  = attn0[off + 32];
                attn0[off]      = __expf(la  - m0a) * i0a;
                attn0[off + 32] = __expf(lb  - m0b) * i0b;
                float la1 = attn1[off], lb1 = attn1[off + 32];
                attn1[off]      = __expf(la1 - m1a) * i1a;
                attn1[off + 32] = __expf(lb1 - m1b) * i1b;
            }
        }
        __syncthreads();   // tile-unit boundary: smem safe to restage
    }
}

// ---------------------------------------------------------------------------
extern "C" void kernel_launch(void* const* d_in, const int* in_sizes, int n_in,
                              void* d_out, int out_size) {
    const float* q  = (const float*)d_in[0];
    const float* kv = (const float*)d_in[1];
    const float* Wq = (const float*)d_in[2];
    const float* bq = (const float*)d_in[3];
    const float* Wk = (const float*)d_in[4];
    const float* bk = (const float*)d_in[5];
    const float* Wv = (const float*)d_in[6];
    const float* bv = (const float*)d_in[7];
    float* out = (float*)d_out;

    cudaFuncSetAttribute(deform_attn_kernel,
                         cudaFuncAttributeMaxDynamicSharedMemorySize, 198144);

    transpose_w_kernel<<<192, 256>>>(Wq, Wk, Wv);
    deform_attn_kernel<<<dim3(GRID_X), 256, 198144>>>(q, kv, bq, bk, bv, out);
}

// round 7
// speedup vs baseline: 1.0044x; 1.0044x over previous
#include <cuda_runtime.h>

// ---------------------------------------------------------------------------
// DeformAttnwMotion fused kernel, round 5
//   R4 -> R5 changes:
//   1. Weight smem loads via LDS.128 (ulonglong2) -> smem crossbar no longer
//      the binding pipe (48 vs 64 fma cycles per c per SM).
//   2. grid = 128 persistent-ish blocks x 2 tile-units -> exactly 1 wave,
//      no 256/148 quantization penalty; Wk staged once per block.
//
// b=4, c=128, d=4096 (64x64), S=18 samples, OUT_C=128, 8 heads x 16 ch.
// Output layout in d_out (float32):
//   [0 , 2097152)            out      : (4,128,64,64)
//   [2097152 , 3276800)      kv0_attn : (32, 9, 4096)
//   [3276800 , 4456448)      kv1_attn : (32, 9, 4096)
// ---------------------------------------------------------------------------

typedef unsigned long long ull;

#define BB   4
#define CC   128
#define DD   4096
#define SS   18
#define OCH  128
#define NHD  8
#define HCH  16
#define FT   64            // pixels per tile-unit
#define UNITS_PER_BLOCK 2
#define GRID_X 128         // 256 units / 2
#define SCALE_F 0.25f

// Transposed weights scratch: [m][c][oc], m = 0:Wq 1:Wk 2:Wv
__device__ float g_WT[3 * CC * OCH];

__global__ void transpose_w_kernel(const float* __restrict__ Wq,
                                   const float* __restrict__ Wk,
                                   const float* __restrict__ Wv) {
    int idx = blockIdx.x * blockDim.x + threadIdx.x;       // 0 .. 49151
    if (idx >= 3 * CC * OCH) return;
    int m   = idx >> 14;
    int rem = idx & 16383;
    int r   = rem >> 7;     // oc
    int c   = rem & 127;    // c
    const float* W = (m == 0) ? Wq : (m == 1) ? Wk : Wv;
    g_WT[m * 16384 + c * OCH + r] = W[r * CC + c];
}

// ---------------- packed f32x2 helpers ----------------
__device__ __forceinline__ ull pack2(float lo, float hi) {
    ull r;
    asm("mov.b64 %0, {%1, %2};" : "=l"(r) : "f"(lo), "f"(hi));
    return r;
}
__device__ __forceinline__ float2 unpack2(ull v) {
    float2 r;
    asm("mov.b64 {%0, %1}, %2;" : "=f"(r.x), "=f"(r.y) : "l"(v));
    return r;
}
__device__ __forceinline__ ull fma2(ull a, ull b, ull c) {
    ull d;
    asm("fma.rn.f32x2 %0, %1, %2, %3;" : "=l"(d) : "l"(a), "l"(b), "l"(c));
    return d;
}
__device__ __forceinline__ ull mul2(ull a, ull b) {
    ull d;
    asm("mul.rn.f32x2 %0, %1, %2;" : "=l"(d) : "l"(a), "l"(b));
    return d;
}
__device__ __forceinline__ void cp16(float* dst, const float* src) {
    unsigned sa = (unsigned)__cvta_generic_to_shared(dst);
    asm volatile("cp.async.cg.shared.global [%0], [%1], 16;" :: "r"(sa), "l"(src));
}

// GEMM micro-pass: ra/rb[p] += W^T[c][oc0+2p..2p+1] * X[c][fi | fi+32]
// Weights read as LDS.128 (2 packed f32x2 per load). 16 FMA2 / c / thread.
__device__ __forceinline__ void proj_pass(const float* __restrict__ Wt,
                                          const float* __restrict__ X,
                                          int fi, int oc0,
                                          ull ra[8], ull rb[8]) {
#pragma unroll 8
    for (int c = 0; c < CC; ++c) {
        float xa = X[c * FT + fi];
        float xb = X[c * FT + fi + 32];
        ull xa2 = pack2(xa, xa);
        ull xb2 = pack2(xb, xb);
        const ulonglong2* wr =
            reinterpret_cast<const ulonglong2*>(Wt + c * OCH + oc0);
#pragma unroll
        for (int p = 0; p < 4; ++p) {
            ulonglong2 w = wr[p];               // LDS.128: 4 weight floats
            ra[2 * p]     = fma2(w.x, xa2, ra[2 * p]);
            rb[2 * p]     = fma2(w.x, xb2, rb[2 * p]);
            ra[2 * p + 1] = fma2(w.y, xa2, ra[2 * p + 1]);
            rb[2 * p + 1] = fma2(w.y, xb2, rb[2 * p + 1]);
        }
    }
}

__global__ void __launch_bounds__(256, 1)
deform_attn_kernel(const float* __restrict__ q,
                   const float* __restrict__ kv,
                   const float* __restrict__ bq,
                   const float* __restrict__ bk,
                   const float* __restrict__ bv,
                   float* __restrict__ out) {
    extern __shared__ float smem[];
    float* sWk = smem;               // 16384 floats : Wk^T [c][oc], whole block life
    float* sWv = smem + 16384;       // 16384 floats : Wq^T then Wv^T (per tile)
    float* sX0 = smem + 32768;       // 8192 : q tile, then kv ping buffer
    float* sX1 = smem + 40960;       // 8192 : kv pong buffer
    float* sB  = smem + 49152;       // 384  : bq | bk | bv

    const int t   = threadIdx.x;     // 256 threads
    const int fi  = t & 31;          // pixel lane; thread owns fi and fi+32
    const int g   = t >> 5;          // head 0..7
    const int oc0 = g * HCH;

    float* attn0 = out + (size_t)BB * OCH * DD;             // 2097152
    float* attn1 = attn0 + (size_t)BB * NHD * 9 * DD;       // +1179648

    // ------------- once per block: Wk^T + biases -----------------------------
    {
        const float4* gk = reinterpret_cast<const float4*>(g_WT + 16384); // WkT
        float4* dk = reinterpret_cast<float4*>(sWk);
#pragma unroll
        for (int i = 0; i < 16; ++i) {
            int idx = t + i * 256;
            dk[idx] = gk[idx];
        }
        if (t < 128) {
            sB[t]       = bq[t];
            sB[128 + t] = bk[t];
            sB[256 + t] = bv[t];
        }
    }

    // ------------- tile-unit loop (2 units, one wave, perfectly balanced) ----
    for (int it = 0; it < UNITS_PER_BLOCK; ++it) {
        const int unit = blockIdx.x + it * GRID_X;   // 0..255
        const int b    = unit >> 6;                  // batch
        const int f0   = (unit & 63) * FT;           // pixel-tile origin

        // phase 0: Wq^T -> sWv, q tile -> sX0, kv(s=0) -> sX1 (async)
        {
            const float4* gq = reinterpret_cast<const float4*>(g_WT);   // WqT
            float4* dq = reinterpret_cast<float4*>(sWv);
#pragma unroll
            for (int i = 0; i < 16; ++i) {
                int idx = t + i * 256;
                dq[idx] = gq[idx];
            }
#pragma unroll
            for (int i = 0; i < 8; ++i) {
                int idx = t + i * 256;
                int c = idx >> 4, f4 = idx & 15;
                reinterpret_cast<float4*>(sX0 + c * FT)[f4] =
                    reinterpret_cast<const float4*>(
                        q + ((size_t)(b * CC + c)) * DD + f0)[f4];
            }
#pragma unroll
            for (int i = 0; i < 8; ++i) {
                int idx = t + i * 256;
                int c = idx >> 4, f4 = idx & 15;
                cp16(sX1 + c * FT + f4 * 4,
                     kv + (((size_t)(b * CC + c)) * SS + 0) * DD + f0 + f4 * 4);
            }
            asm volatile("cp.async.commit_group;" ::: "memory");
        }
        __syncthreads();

        // q projection (sWv holds Wq^T)
        ull qpa[8], qpb[8];
#pragma unroll
        for (int p = 0; p < 8; ++p) {
            ull bb = pack2(sB[oc0 + 2 * p], sB[oc0 + 2 * p + 1]);
            qpa[p] = bb; qpb[p] = bb;
        }
        proj_pass(sWv, sX0, fi, oc0, qpa, qpb);
        __syncthreads();                 // done reading Wq^T and q tile

        {   // overwrite with Wv^T
            const float4* gv = reinterpret_cast<const float4*>(g_WT + 32768);
            float4* dv = reinterpret_cast<float4*>(sWv);
#pragma unroll
            for (int i = 0; i < 16; ++i) {
                int idx = t + i * 256;
                dv[idx] = gv[idx];
            }
        }
        __syncthreads();

        // online-softmax state
        const float NEG = -1e30f;
        float m_a = NEG, Z_a = 0.f, m_b = NEG, Z_b = 0.f;   // full softmax
        float m0a = NEG, Z0a = 0.f, m1a = NEG, Z1a = 0.f;   // half trackers px a
        float m0b = NEG, Z0b = 0.f, m1b = NEG, Z1b = 0.f;   // half trackers px b
        ull acc_a[8], acc_b[8];
#pragma unroll
        for (int p = 0; p < 8; ++p) { acc_a[p] = 0ull; acc_b[p] = 0ull; }

        // main sample loop
        for (int s = 0; s < SS; ++s) {
            float* cur = (s & 1) ? sX0 : sX1;
            float* nxt = (s & 1) ? sX1 : sX0;
            if (s < SS - 1) {
#pragma unroll
                for (int i = 0; i < 8; ++i) {
                    int idx = t + i * 256;
                    int c = idx >> 4, f4 = idx & 15;
                    cp16(nxt + c * FT + f4 * 4,
                         kv + (((size_t)(b * CC + c)) * SS + (s + 1)) * DD
                            + f0 + f4 * 4);
                }
                asm volatile("cp.async.commit_group;" ::: "memory");
                asm volatile("cp.async.wait_group 1;" ::: "memory");
            } else {
                asm volatile("cp.async.wait_group 0;" ::: "memory");
            }
            __syncthreads();

            // ---- K projection ----
            ull ka[8], kb[8];
#pragma unroll
            for (int p = 0; p < 8; ++p) {
                ull bbk = pack2(sB[128 + oc0 + 2 * p], sB[128 + oc0 + 2 * p + 1]);
                ka[p] = bbk; kb[p] = bbk;
            }
            proj_pass(sWk, cur, fi, oc0, ka, kb);

            // ---- logits ----
            ull da = 0ull, db = 0ull;
#pragma unroll
            for (int p = 0; p < 8; ++p) {
                da = fma2(qpa[p], ka[p], da);
                db = fma2(qpb[p], kb[p], db);
            }
            float2 dau = unpack2(da), dbu = unpack2(db);
            float a_a = (dau.x + dau.y) * SCALE_F;
            float a_b = (dbu.x + dbu.y) * SCALE_F;

            // stage raw logits into the attn output region (same thread re-reads)
            {
                float* base = (s < 9) ? attn0 : attn1;
                int ss = (s < 9) ? s : s - 9;
                size_t off = ((size_t)(b * NHD + g) * 9 + ss) * DD + f0 + fi;
                base[off]      = a_a;
                base[off + 32] = a_b;
            }

            // ---- per-half online (m, Z) ----
            if (s < 9) {
                float nm = fmaxf(m0a, a_a);
                Z0a = Z0a * __expf(m0a - nm) + __expf(a_a - nm); m0a = nm;
                nm = fmaxf(m0b, a_b);
                Z0b = Z0b * __expf(m0b - nm) + __expf(a_b - nm); m0b = nm;
            } else {
                float nm = fmaxf(m1a, a_a);
                Z1a = Z1a * __expf(m1a - nm) + __expf(a_a - nm); m1a = nm;
                nm = fmaxf(m1b, a_b);
                Z1b = Z1b * __expf(m1b - nm) + __expf(a_b - nm); m1b = nm;
            }

            // ---- full online softmax rescale ----
            float nma = fmaxf(m_a, a_a);
            float caf = __expf(m_a - nma), paf = __expf(a_a - nma);
            Z_a = Z_a * caf + paf; m_a = nma;
            float nmb = fmaxf(m_b, a_b);
            float cbf = __expf(m_b - nmb), pbf = __expf(a_b - nmb);
            Z_b = Z_b * cbf + pbf; m_b = nmb;

            ull ca2 = pack2(caf, caf), pa2 = pack2(paf, paf);
            ull cb2 = pack2(cbf, cbf), pb2 = pack2(pbf, pbf);

            // ---- V projection (reuse ka/kb as vp) ----
#pragma unroll
            for (int p = 0; p < 8; ++p) {
                ull bbv = pack2(sB[256 + oc0 + 2 * p], sB[256 + oc0 + 2 * p + 1]);
                ka[p] = bbv; kb[p] = bbv;
            }
            proj_pass(sWv, cur, fi, oc0, ka, kb);

            // acc = acc*corr + vp*p
#pragma unroll
            for (int p = 0; p < 8; ++p) {
                acc_a[p] = fma2(acc_a[p], ca2, mul2(ka[p], pa2));
                acc_b[p] = fma2(acc_b[p], cb2, mul2(kb[p], pb2));
            }
            __syncthreads();    // all readers of 'cur' done before refill
        }

        // epilogue: out = acc / Z
        {
            float ia = 1.f / Z_a, ib = 1.f / Z_b;
#pragma unroll
            for (int p = 0; p < 8; ++p) {
                float2 oa = unpack2(acc_a[p]);
                float2 ob = unpack2(acc_b[p]);
                size_t r0 = ((size_t)(b * OCH + oc0 + 2 * p)) * DD + f0 + fi;
                size_t r1 = r0 + DD;
                out[r0]      = oa.x * ia;
                out[r1]      = oa.y * ia;
                out[r0 + 32] = ob.x * ib;
                out[r1 + 32] = ob.y * ib;
            }
        }

        // epilogue: half softmaxes over staged logits
        {
            float i0a = 1.f / Z0a, i1a = 1.f / Z1a;
            float i0b = 1.f / Z0b, i1b = 1.f / Z1b;
            size_t baseoff = ((size_t)(b * NHD + g) * 9) * DD + f0 + fi;
#pragma unroll
            for (int ss = 0; ss < 9; ++ss) {
                size_t off = baseoff + (size_t)ss * DD;
                float la  = attn0[off], lb  = attn0[off + 32];
                attn0[off]      = __expf(la  - m0a) * i0a;
                attn0[off + 32] = __expf(lb  - m0b) * i0b;
                float la1 = attn1[off], lb1 = attn1[off + 32];
                attn1[off]      = __expf(la1 - m1a) * i1a;
                attn1[off + 32] = __expf(lb1 - m1b) * i1b;
            }
        }
        __syncthreads();   // tile-unit boundary: smem safe to restage
    }
}

// ---------------------------------------------------------------------------
extern "C" void kernel_launch(void* const* d_in, const int* in_sizes, int n_in,
                              void* d_out, int out_size) {
    const float* q  = (const float*)d_in[0];
    const float* kv = (const float*)d_in[1];
    const float* Wq = (const float*)d_in[2];
    const float* bq = (const float*)d_in[3];
    const float* Wk = (const float*)d_in[4];
    const float* bk = (const float*)d_in[5];
    const float* Wv = (const float*)d_in[6];
    const float* bv = (const float*)d_in[7];
    float* out = (float*)d_out;

    cudaFuncSetAttribute(deform_attn_kernel,
                         cudaFuncAttributeMaxDynamicSharedMemorySize, 198144);

    transpose_w_kernel<<<192, 256>>>(Wq, Wk, Wv);
    deform_attn_kernel<<<dim3(GRID_X), 256, 198144>>>(q, kv, bq, bk, bv, out);
}

// round 8
// speedup vs baseline: 2.5359x; 2.5248x over previous
#include <cuda_runtime.h>

// ---------------------------------------------------------------------------
// DeformAttnwMotion, round 7: algebraic restructure.
//   logit_s = (Wk_h^T qp_h) . kv_s   (+const in s -> drops out of softmax)
//   out_h   = Wv_h . (sum_s w_s kv_s)/Z + bv
// Arithmetic 9.9 GMAC -> 1.4 GMAC. kv read exactly once from HBM.
//
// Tile = 16 pixels. 256 threads. Thread (px, cgrp) owns qtilde[8h][8c] and
// agg[8h][8c] in registers. Logits reduced across 16 cgrps via smem.
// Logits are O(1) -> plain expf, no max subtraction needed.
//
// d_out layout (float32):
//   [0 , 2097152)            out      : (4,128,64,64)
//   [2097152 , 3276800)      kv0_attn : (32, 9, 4096)
//   [3276800 , 4456448)      kv1_attn : (32, 9, 4096)
// ---------------------------------------------------------------------------

typedef unsigned long long ull;

#define BB   4
#define CC   128
#define DD   4096
#define SS   18
#define OCH  128
#define NHD  8
#define TPX  16
#define SCALE_F 0.25f

// Transposed weights scratch: [m][c][oc], m = 0:Wq 1:Wk 2:Wv
__device__ float g_WT[3 * CC * OCH];

__global__ void transpose_w_kernel(const float* __restrict__ Wq,
                                   const float* __restrict__ Wk,
                                   const float* __restrict__ Wv) {
    int idx = blockIdx.x * blockDim.x + threadIdx.x;
    if (idx >= 3 * CC * OCH) return;
    int m   = idx >> 14;
    int rem = idx & 16383;
    int r   = rem >> 7;     // oc
    int c   = rem & 127;    // c
    const float* W = (m == 0) ? Wq : (m == 1) ? Wk : Wv;
    g_WT[m * 16384 + c * OCH + r] = W[r * CC + c];
}

// ---------------- packed f32x2 helpers ----------------
__device__ __forceinline__ ull pack2(float lo, float hi) {
    ull r; asm("mov.b64 %0, {%1, %2};" : "=l"(r) : "f"(lo), "f"(hi)); return r;
}
__device__ __forceinline__ float2 unpack2(ull v) {
    float2 r; asm("mov.b64 {%0, %1}, %2;" : "=f"(r.x), "=f"(r.y) : "l"(v)); return r;
}
__device__ __forceinline__ ull fma2(ull a, ull b, ull c) {
    ull d; asm("fma.rn.f32x2 %0, %1, %2, %3;" : "=l"(d) : "l"(a), "l"(b), "l"(c)); return d;
}
__device__ __forceinline__ void cp16(float* dst, const float* src) {
    unsigned sa = (unsigned)__cvta_generic_to_shared(dst);
    asm volatile("cp.async.cg.shared.global [%0], [%1], 16;" :: "r"(sa), "l"(src));
}
#define CP_COMMIT() asm volatile("cp.async.commit_group;" ::: "memory")
#define CP_WAIT(n)  asm volatile("cp.async.wait_group %0;" :: "n"(n) : "memory")

// smem float offsets
#define SM_W    0          // 16384 : Wq^T, later Wv^T
#define SM_WB   16384      // 16384 : Wk^T, later agg[h][px][c]
#define SM_QP   32768      // 2048  : qp[oc][px], later logit partials [h][cgrp][px]
#define SM_LOG  34816      // 2304  : logits [h][s][px]
#define SM_WGT  37120      // 128   : per-sample w[h][px], later invZ[h][px]
#define SM_KV   37248      // 4096  : kv double buffer [2][c][px]
#define SM_TOTAL_F 41344   // floats (165376 bytes)

__global__ void __launch_bounds__(256, 1)
deform_attn_kernel(const float* __restrict__ q,
                   const float* __restrict__ kv,
                   const float* __restrict__ bq,
                   const float* __restrict__ bk,   // unused (softmax shift-inv)
                   const float* __restrict__ bv,
                   float* __restrict__ out) {
    extern __shared__ float sm[];

    const int t   = threadIdx.x;     // 256
    const int px  = t & 15;          // pixel in tile
    const int cg  = t >> 4;          // c-group 0..15 (8 channels each)
    const int c0  = cg * 8;
    const int b   = blockIdx.y;
    const int pxg = blockIdx.x * TPX;

    float* attn0 = out + (size_t)BB * OCH * DD;
    float* attn1 = attn0 + (size_t)BB * NHD * 9 * DD;

    // ---- P0: async stage WqT + q tile (A), WkT (B), kv s=0 (C) -------------
    {
        // A: WqT -> SM_W (64KB) and q tile -> kv buf0
#pragma unroll
        for (int k = 0; k < 16; ++k) {
            int i = t + k * 256;
            cp16(sm + SM_W + i * 4, g_WT + i * 4);
        }
#pragma unroll
        for (int k = 0; k < 2; ++k) {
            int i = t + k * 256;                    // 0..511
            int c = i >> 2, seg = i & 3;
            cp16(sm + SM_KV + c * 16 + seg * 4,
                 q + ((size_t)(b * CC + c)) * DD + pxg + seg * 4);
        }
        CP_COMMIT();   // group A
        // B: WkT -> SM_WB
#pragma unroll
        for (int k = 0; k < 16; ++k) {
            int i = t + k * 256;
            cp16(sm + SM_WB + i * 4, g_WT + 16384 + i * 4);
        }
        CP_COMMIT();   // group B
        // C: kv s=0 -> kv buf1
#pragma unroll
        for (int k = 0; k < 2; ++k) {
            int i = t + k * 256;
            int c = i >> 2, seg = i & 3;
            cp16(sm + SM_KV + 2048 + c * 16 + seg * 4,
                 kv + (((size_t)(b * CC + c)) * SS + 0) * DD + pxg + seg * 4);
        }
        CP_COMMIT();   // group C
    }
    CP_WAIT(2);        // A done
    __syncthreads();

    // ---- P1: qp[oc][px] = Wq.x + bq  (thread = (ocg=cg, px), 8 oc each) ----
    {
        const int oc0 = cg * 8;
        ull acc[4];
#pragma unroll
        for (int u = 0; u < 4; ++u)
            acc[u] = pack2(bq[oc0 + 2 * u], bq[oc0 + 2 * u + 1]);
#pragma unroll 4
        for (int c = 0; c < CC; ++c) {
            float qv = sm[SM_KV + c * 16 + px];
            ull q2 = pack2(qv, qv);
            const ull* wr = reinterpret_cast<const ull*>(sm + SM_W + c * OCH + oc0);
#pragma unroll
            for (int u = 0; u < 4; ++u) acc[u] = fma2(wr[u], q2, acc[u]);
        }
#pragma unroll
        for (int u = 0; u < 4; ++u) {
            float2 v = unpack2(acc[u]);
            sm[SM_QP + (oc0 + 2 * u) * 16 + px]     = v.x;
            sm[SM_QP + (oc0 + 2 * u + 1) * 16 + px] = v.y;
        }
    }
    __syncthreads();   // qp visible; SM_W (WqT) and kv buf0 (q) free

    // D: WvT -> SM_W (overlaps with everything until P5)
#pragma unroll
    for (int k = 0; k < 16; ++k) {
        int i = t + k * 256;
        cp16(sm + SM_W + i * 4, g_WT + 32768 + i * 4);
    }
    CP_COMMIT();       // group D
    CP_WAIT(2);        // B (WkT) done; C,D may be pending

    // ---- P2: qtilde[h][c0..c0+7] into registers ----------------------------
    // qtilde[h][c] = sum_j WkT[c][h*16+j] * qp[h*16+j][px]
    ull qt2[NHD][4];
    {
#pragma unroll
        for (int h = 0; h < NHD; ++h) {
            ull qp2[8];
#pragma unroll
            for (int j = 0; j < 8; ++j)
                qp2[j] = pack2(sm[SM_QP + (h * 16 + 2 * j) * 16 + px],
                               sm[SM_QP + (h * 16 + 2 * j + 1) * 16 + px]);
            float qts[8];
#pragma unroll
            for (int i = 0; i < 8; ++i) {
                int c = c0 + i;
                const ull* wr =
                    reinterpret_cast<const ull*>(sm + SM_WB + c * OCH + h * 16);
                ull a = 0ull;
#pragma unroll
                for (int j = 0; j < 8; ++j) a = fma2(wr[j], qp2[j], a);
                float2 v = unpack2(a);
                qts[i] = v.x + v.y;
            }
#pragma unroll
            for (int u = 0; u < 4; ++u)
                qt2[h][u] = pack2(qts[2 * u], qts[2 * u + 1]);
        }
    }

    // ---- P4: sample loop ----------------------------------------------------
    ull agg2[NHD][4];
#pragma unroll
    for (int h = 0; h < NHD; ++h)
#pragma unroll
        for (int u = 0; u < 4; ++u) agg2[h][u] = 0ull;

    float Zf = 0.f, Z0 = 0.f, Z1 = 0.f;            // live in t<128 threads
    const int rh = t >> 4;                          // reducer head (t<128)
    const int rp = t & 15;                          // reducer pixel

    for (int s = 0; s < SS; ++s) {
        float* cur = sm + SM_KV + ((s + 1) & 1) * 2048;
        if (s < SS - 1) {
            float* nxt = sm + SM_KV + (s & 1) * 2048;
#pragma unroll
            for (int k = 0; k < 2; ++k) {
                int i = t + k * 256;
                int c = i >> 2, seg = i & 3;
                cp16(nxt + c * 16 + seg * 4,
                     kv + (((size_t)(b * CC + c)) * SS + (s + 1)) * DD
                        + pxg + seg * 4);
            }
            CP_COMMIT();
        }
        if (s == 0)          { CP_WAIT(2); }   // C done (D, pre1 may pend)
        else if (s < SS - 1) { CP_WAIT(1); }   // kv(s) done
        else                 { CP_WAIT(0); }   // everything incl. D (WvT)
        __syncthreads();

        // kv channels for this thread (kept for agg step)
        ull kv2[4];
#pragma unroll
        for (int u = 0; u < 4; ++u)
            kv2[u] = pack2(cur[(c0 + 2 * u) * 16 + px],
                           cur[(c0 + 2 * u + 1) * 16 + px]);

        // partial logits per head -> smem
#pragma unroll
        for (int h = 0; h < NHD; ++h) {
            ull a = 0ull;
#pragma unroll
            for (int u = 0; u < 4; ++u) a = fma2(qt2[h][u], kv2[u], a);
            float2 v = unpack2(a);
            sm[SM_QP + h * 256 + cg * 16 + px] = v.x + v.y;
        }
        __syncthreads();

        // reduce 16 partials, exp, store logit + weight
        if (t < 128) {
            float sum = 0.f;
#pragma unroll
            for (int j = 0; j < 16; ++j)
                sum += sm[SM_QP + rh * 256 + j * 16 + rp];
            float lg = sum * SCALE_F;
            sm[SM_LOG + rh * (SS * 16) + s * 16 + rp] = lg;
            float w = __expf(lg);
            sm[SM_WGT + rh * 16 + rp] = w;
            Zf += w;
            if (s < 9) Z0 += w; else Z1 += w;
        }
        __syncthreads();

        // agg[h] += w[h] * kv
#pragma unroll
        for (int h = 0; h < NHD; ++h) {
            float w = sm[SM_WGT + h * 16 + px];
            ull w2 = pack2(w, w);
#pragma unroll
            for (int u = 0; u < 4; ++u)
                agg2[h][u] = fma2(kv2[u], w2, agg2[h][u]);
        }
    }
    __syncthreads();   // last sWGT read done before invZ overwrite

    // ---- stage agg -> smem (SM_WB now free), invZ -> SM_WGT ------------------
    if (t < 128) sm[SM_WGT + rh * 16 + rp] = 1.f / Zf;
    {
        float2* dst;
#pragma unroll
        for (int h = 0; h < NHD; ++h) {
            dst = reinterpret_cast<float2*>(sm + SM_WB + h * 2048 + px * 128 + c0);
#pragma unroll
            for (int u = 0; u < 4; ++u) dst[u] = unpack2(agg2[h][u]);
        }
    }
    __syncthreads();

    // ---- P5: out[oc][px] = (WvT^T . agg_h) * invZ + bv ----------------------
    {
        const int oc0 = cg * 8;
        const int h   = cg >> 1;
        ull acc[4];
#pragma unroll
        for (int u = 0; u < 4; ++u) acc[u] = 0ull;
        const float* aggp = sm + SM_WB + h * 2048 + px * 128;
#pragma unroll 8
        for (int c = 0; c < CC; c += 2) {
            float2 a = *reinterpret_cast<const float2*>(aggp + c);
            ull a0 = pack2(a.x, a.x);
            ull a1 = pack2(a.y, a.y);
            const ull* w0 = reinterpret_cast<const ull*>(sm + SM_W + c * OCH + oc0);
            const ull* w1 = reinterpret_cast<const ull*>(sm + SM_W + (c + 1) * OCH + oc0);
#pragma unroll
            for (int u = 0; u < 4; ++u) {
                acc[u] = fma2(w0[u], a0, acc[u]);
                acc[u] = fma2(w1[u], a1, acc[u]);
            }
        }
        float iz = sm[SM_WGT + h * 16 + px];
#pragma unroll
        for (int u = 0; u < 4; ++u) {
            float2 v = unpack2(acc[u]);
            int oc = oc0 + 2 * u;
            out[((size_t)(b * OCH + oc)) * DD + pxg + px]     = v.x * iz + bv[oc];
            out[((size_t)(b * OCH + oc + 1)) * DD + pxg + px] = v.y * iz + bv[oc + 1];
        }
    }

    // ---- epilogue: half softmaxes from smem logits --------------------------
    if (t < 128) {
        float iz0 = 1.f / Z0, iz1 = 1.f / Z1;
        size_t base = ((size_t)(b * NHD + rh) * 9) * DD + pxg + rp;
#pragma unroll
        for (int s = 0; s < 9; ++s) {
            attn0[base + (size_t)s * DD] =
                __expf(sm[SM_LOG + rh * (SS * 16) + s * 16 + rp]) * iz0;
            attn1[base + (size_t)s * DD] =
                __expf(sm[SM_LOG + rh * (SS * 16) + (s + 9) * 16 + rp]) * iz1;
        }
    }
}

// ---------------------------------------------------------------------------
extern "C" void kernel_launch(void* const* d_in, const int* in_sizes, int n_in,
                              void* d_out, int out_size) {
    const float* q  = (const float*)d_in[0];
    const float* kv = (const float*)d_in[1];
    const float* Wq = (const float*)d_in[2];
    const float* bq = (const float*)d_in[3];
    const float* Wk = (const float*)d_in[4];
    const float* bk = (const float*)d_in[5];
    const float* Wv = (const float*)d_in[6];
    const float* bv = (const float*)d_in[7];
    float* out = (float*)d_out;

    cudaFuncSetAttribute(deform_attn_kernel,
                         cudaFuncAttributeMaxDynamicSharedMemorySize,
                         SM_TOTAL_F * 4);

    transpose_w_kernel<<<192, 256>>>(Wq, Wk, Wv);
    deform_attn_kernel<<<dim3(DD / TPX, BB), 256, SM_TOTAL_F * 4>>>(
        q, kv, bq, bk, bv, out);
}